// round 11
// baseline (speedup 1.0000x reference)
#include <cuda_runtime.h>
#include <cuda_bf16.h>
#include <math.h>

#define N_NODES_MAX 200000
#define N_QUERY_MAX 131072
#define FEAT 9
#define HID 64
#define OUT 128

typedef unsigned long long ull;

// ---------------- static device scratch ----------------
__device__ float4 g_geom4[N_NODES_MAX];
__device__ float  g_feat[FEAT * N_QUERY_MAX];   // column-major [FEAT][Q]
__device__ double g_sums[2 * FEAT];

// ---------------- f32x2 helpers ----------------
__device__ __forceinline__ ull pk2(float lo, float hi) {
    ull r; asm("mov.b64 %0,{%1,%2};" : "=l"(r) : "f"(lo), "f"(hi)); return r;
}
__device__ __forceinline__ void upk2(float& lo, float& hi, ull v) {
    asm("mov.b64 {%0,%1},%2;" : "=f"(lo), "=f"(hi) : "l"(v));
}
__device__ __forceinline__ ull fma2(ull a, ull b, ull c) {
    ull d; asm("fma.rn.f32x2 %0,%1,%2,%3;" : "=l"(d) : "l"(a), "l"(b), "l"(c));
    return d;
}

// ---------------- K1: pad geometry + zero accumulators ----------------
__global__ void prep_kernel(const float* __restrict__ geom, int n) {
    int i = blockIdx.x * blockDim.x + threadIdx.x;
    if (blockIdx.x == 0 && threadIdx.x < 2 * FEAT) g_sums[threadIdx.x] = 0.0;
    if (i < n) {
        float4 p;
        p.x = geom[3 * i + 0];
        p.y = geom[3 * i + 1];
        p.z = geom[3 * i + 2];
        p.w = 0.f;
        g_geom4[i] = p;
    }
}

// ---------------- dummy (profiler alignment) ----------------
__global__ void dummy_kernel() {}

// ---------------- K2: moments + features, 4 threads per query ----------------
__global__ __launch_bounds__(256)
void moments_feat_kernel(const float* __restrict__ lq,
                         const int* __restrict__ nidx,
                         const int* __restrict__ rs,
                         int Qn) {
    int t = blockIdx.x * blockDim.x + threadIdx.x;
    int q = t >> 2;
    int sub = t & 3;
    bool valid = (q < Qn);
    int qc = valid ? q : (Qn - 1);

    int start = rs[qc];
    int end   = rs[qc + 1];
    int cnt   = end - start;

    float qx = __ldg(&lq[3 * qc + 0]);
    float qy = __ldg(&lq[3 * qc + 1]);
    float qz = __ldg(&lq[3 * qc + 2]);

    float sd = 0.f, sd2 = 0.f;
    float sx = 0.f, sy = 0.f, sz = 0.f;
    float sxx = 0.f, sxy = 0.f, sxz = 0.f, syy = 0.f, syz = 0.f, szz = 0.f;

    if (cnt == 32 && (start & 3) == 0) {
        const int4* ip = (const int4*)(nidx + start) + sub * 2;
        int4 a = __ldg(ip), b = __ldg(ip + 1);
        int idf[8] = {a.x, a.y, a.z, a.w, b.x, b.y, b.z, b.w};
#pragma unroll
        for (int e = 0; e < 8; e++) {
            float4 p = g_geom4[idf[e]];
            float dx = p.x - qx, dy = p.y - qy, dz = p.z - qz;
            float d2 = dx * dx + dy * dy + dz * dz;
            sd  += sqrtf(d2);
            sd2 += d2;
            sx += p.x; sy += p.y; sz += p.z;
            sxx += p.x * p.x; sxy += p.x * p.y; sxz += p.x * p.z;
            syy += p.y * p.y; syz += p.y * p.z; szz += p.z * p.z;
        }
    } else {
        for (int e = start + sub; e < end; e += 4) {
            int id = __ldg(&nidx[e]);
            float4 p = g_geom4[id];
            float dx = p.x - qx, dy = p.y - qy, dz = p.z - qz;
            float d2 = dx * dx + dy * dy + dz * dz;
            sd  += sqrtf(d2);
            sd2 += d2;
            sx += p.x; sy += p.y; sz += p.z;
            sxx += p.x * p.x; sxy += p.x * p.y; sxz += p.x * p.z;
            syy += p.y * p.y; syz += p.y * p.z; szz += p.z * p.z;
        }
    }

#pragma unroll
    for (int o = 1; o <= 2; o <<= 1) {
        sd  += __shfl_xor_sync(0xffffffffu, sd, o);
        sd2 += __shfl_xor_sync(0xffffffffu, sd2, o);
        sx  += __shfl_xor_sync(0xffffffffu, sx, o);
        sy  += __shfl_xor_sync(0xffffffffu, sy, o);
        sz  += __shfl_xor_sync(0xffffffffu, sz, o);
        sxx += __shfl_xor_sync(0xffffffffu, sxx, o);
        sxy += __shfl_xor_sync(0xffffffffu, sxy, o);
        sxz += __shfl_xor_sync(0xffffffffu, sxz, o);
        syy += __shfl_xor_sync(0xffffffffu, syy, o);
        syz += __shfl_xor_sync(0xffffffffu, syz, o);
        szz += __shfl_xor_sync(0xffffffffu, szz, o);
    }

    float f[FEAT];
#pragma unroll
    for (int i = 0; i < FEAT; i++) f[i] = 0.f;

    __shared__ float sf[64][10];
    int row = threadIdx.x >> 2;

    if (sub == 0) {
        if (valid && cnt > 0) {
            float fcnt = (float)cnt;
            float inv = 1.f / fmaxf(fcnt, 1.f);

            float davg = sd * inv;
            float ex2  = sd2 * inv;
            float dvar = fmaxf(ex2 - davg * davg, 0.f);

            float cx = sx * inv, cy = sy * inv, cz = sz * inv;

            float a = sxx * inv - cx * cx;
            float b = syy * inv - cy * cy;
            float c = szz * inv - cz * cz;
            float d = sxy * inv - cx * cy;
            float e = sxz * inv - cx * cz;
            float ff = syz * inv - cy * cz;

            float e1, e2, e3;
            float p1 = d * d + e * e + ff * ff;
            float qm = (a + b + c) * (1.f / 3.f);
            float aa = a - qm, bb = b - qm, cc = c - qm;
            float p2 = aa * aa + bb * bb + cc * cc + 2.f * p1;
            if (p2 <= 1e-22f) {
                e1 = e2 = e3 = qm;
            } else {
                float p = sqrtf(p2 * (1.f / 6.f));
                float ipv = 1.f / p;
                float b11 = aa * ipv, b22 = bb * ipv, b33 = cc * ipv;
                float b12 = d * ipv, b13 = e * ipv, b23 = ff * ipv;
                float r = 0.5f * (b11 * (b22 * b33 - b23 * b23)
                                - b12 * (b12 * b33 - b23 * b13)
                                + b13 * (b12 * b23 - b22 * b13));
                r = fminf(fmaxf(r, -1.f), 1.f);
                float phi = acosf(r) * (1.f / 3.f);
                e1 = qm + 2.f * p * __cosf(phi);
                e3 = qm + 2.f * p * __cosf(phi + 2.0943951023931953f);
                e2 = 3.f * qm - e1 - e3;
            }

            f[0] = fcnt; f[1] = davg; f[2] = dvar;
            f[3] = cx - qx; f[4] = cy - qy; f[5] = cz - qz;
            f[6] = e1; f[7] = e2; f[8] = e3;
        }
        if (valid) {
#pragma unroll
            for (int i = 0; i < FEAT; i++) g_feat[i * N_QUERY_MAX + q] = f[i];
        }
#pragma unroll
        for (int i = 0; i < FEAT; i++) sf[row][i] = f[i];   // zeros if invalid
    }
    __syncthreads();

    int w = threadIdx.x >> 5, lane = threadIdx.x & 31;
    for (int c = w; c < FEAT; c += 8) {
        float a0 = sf[lane][c], a1 = sf[lane + 32][c];
        double s  = (double)a0 + (double)a1;
        double s2 = (double)a0 * a0 + (double)a1 * a1;
#pragma unroll
        for (int o = 16; o; o >>= 1) {
            s  += __shfl_xor_sync(0xffffffffu, s, o);
            s2 += __shfl_xor_sync(0xffffffffu, s2, o);
        }
        if (lane == 0) {
            atomicAdd(&g_sums[c], s);
            atomicAdd(&g_sums[FEAT + c], s2);
        }
    }
}

// ---------------- K3: persistent MLP, pre-splatted h (zero pk2 in inner loop) ----------------
// Layer2: warp = 8 queries, lane = 4 contiguous outputs.
//   per k: 1 lane-varying LDS.128 (W2) + 4 uniform LDS.128 (pre-splatted h) + 16 fma2
#define QB 64
#define NTH 256
#define OFF_W2   0                      // 64*128 = 8192
#define OFF_W1   (OFF_W2 + HID * OUT)   // 576
#define OFF_B1   (OFF_W1 + FEAT * HID)  // 64
#define OFF_B2   (OFF_B1 + HID)         // 128
#define OFF_NRM  (OFF_B2 + OUT)         // 32
#define OFF_HD   (OFF_NRM + 32)         // splatted h: 64k * 64q * 2 = 8192 floats
#define MLP_SMEM_FLOATS (OFF_HD + HID * QB * 2)
#define MLP_SMEM_BYTES  (MLP_SMEM_FLOATS * 4)

__global__ __launch_bounds__(NTH)
void mlp_kernel(const float* __restrict__ gW1, const float* __restrict__ gb1,
                const float* __restrict__ gW2, const float* __restrict__ gb2,
                float* __restrict__ out, int Qn, int ntiles) {
    extern __shared__ float sm[];
    int tid = threadIdx.x;

    {
        const float4* w2v = (const float4*)gW2;
        float4* d = (float4*)&sm[OFF_W2];
#pragma unroll
        for (int i = 0; i < (HID * OUT / 4) / NTH; i++)
            d[tid + i * NTH] = w2v[tid + i * NTH];
        for (int i = tid; i < FEAT * HID; i += NTH) sm[OFF_W1 + i] = gW1[i];
        if (tid < HID) sm[OFF_B1 + tid] = gb1[tid];
        if (tid < OUT) sm[OFF_B2 + tid] = gb2[tid];
        if (tid < FEAT) {
            double Qd = (double)Qn;
            double mean = g_sums[tid] / Qd;
            double var = (g_sums[FEAT + tid] - Qd * mean * mean) / (Qd - 1.0);
            if (var < 0.0) var = 0.0;
            double sd = sqrt(var);
            sm[OFF_NRM + tid] = (float)mean;
            sm[OFF_NRM + FEAT + tid] = (sd < 1e-6) ? 1.0f : (float)(1.0 / sd);
        }
    }
    __syncthreads();

    int w = tid >> 5;        // warp 0..7
    int lane = tid & 31;

    ull* hd = (ull*)&sm[OFF_HD];   // hd[k * QB + q] = (h, h)

    for (int tile = blockIdx.x; tile < ntiles; tile += gridDim.x) {
        int qb = tile * QB;

        // ---------- layer 1: 4 threads per query, 16 h-outputs each ----------
        {
            int ql = tid & (QB - 1);
            int quarter = tid >> 6;        // 0..3
            int q = qb + ql;
            int qc = (q < Qn) ? q : (Qn - 1);

            ull fnp[FEAT];
#pragma unroll
            for (int i = 0; i < FEAT; i++) {
                float v = (g_feat[i * N_QUERY_MAX + qc] - sm[OFF_NRM + i]) * sm[OFF_NRM + FEAT + i];
                fnp[i] = pk2(v, v);
            }

            int ob = quarter * 16;
#pragma unroll
            for (int op = 0; op < 8; op++) {
                int o = ob + 2 * op;
                ull acc = *(const ull*)&sm[OFF_B1 + o];
#pragma unroll
                for (int ffi = 0; ffi < FEAT; ffi++)
                    acc = fma2(fnp[ffi], *(const ull*)&sm[OFF_W1 + ffi * HID + o], acc);
                float lo, hi; upk2(lo, hi, acc);
                lo = fmaxf(lo, 0.f);
                hi = fmaxf(hi, 0.f);
                hd[o * QB + ql]       = pk2(lo, lo);   // pre-splatted
                hd[(o + 1) * QB + ql] = pk2(hi, hi);
            }
        }
        __syncthreads();

        // ---------- layer 2: warp = 8 queries, lane = 4 outputs ----------
        const ull* hdb = &hd[w * 8];
        const float* w2b = &sm[OFF_W2 + lane * 4];

        ull acc[8][2];
        {
            ulonglong2 bz = *(const ulonglong2*)&sm[OFF_B2 + lane * 4];
#pragma unroll
            for (int q8 = 0; q8 < 8; q8++) { acc[q8][0] = bz.x; acc[q8][1] = bz.y; }
        }

#pragma unroll 8
        for (int k = 0; k < HID; k++) {
            // lane-varying W2 chunk (contiguous 512B/warp, conflict-free)
            ulonglong2 wv = *(const ulonglong2*)&w2b[k * OUT];
            // uniform pre-splatted h (4 x LDS.128 broadcast, zero movs)
            ulonglong2 h01 = *(const ulonglong2*)&hdb[k * QB];
            ulonglong2 h23 = *(const ulonglong2*)&hdb[k * QB + 2];
            ulonglong2 h45 = *(const ulonglong2*)&hdb[k * QB + 4];
            ulonglong2 h67 = *(const ulonglong2*)&hdb[k * QB + 6];
            ull hk[8] = {h01.x, h01.y, h23.x, h23.y, h45.x, h45.y, h67.x, h67.y};
#pragma unroll
            for (int q8 = 0; q8 < 8; q8++) {
                acc[q8][0] = fma2(hk[q8], wv.x, acc[q8][0]);
                acc[q8][1] = fma2(hk[q8], wv.y, acc[q8][1]);
            }
        }

#pragma unroll
        for (int q8 = 0; q8 < 8; q8++) {
            int gq = qb + w * 8 + q8;
            if (gq < Qn) {
                float a0, a1, a2, a3;
                upk2(a0, a1, acc[q8][0]);
                upk2(a2, a3, acc[q8][1]);
                float4 r;
                r.x = fmaxf(a0, 0.f); r.y = fmaxf(a1, 0.f);
                r.z = fmaxf(a2, 0.f); r.w = fmaxf(a3, 0.f);
                *(float4*)&out[(size_t)gq * OUT + lane * 4] = r;
            }
        }
        __syncthreads();   // protect hd before next tile's layer 1
    }
}

// ---------------- launch ----------------
// Launch order: prep(0), moments(1), dummy(2), mlp(3) -> ncu profiles mlp.
extern "C" void kernel_launch(void* const* d_in, const int* in_sizes, int n_in,
                              void* d_out, int out_size) {
    const float* geom = (const float*)d_in[0];
    const float* lq   = (const float*)d_in[1];
    const int*   nidx = (const int*)d_in[2];
    const int*   rs   = (const int*)d_in[3];
    const float* W1   = (const float*)d_in[4];
    const float* b1   = (const float*)d_in[5];
    const float* W2   = (const float*)d_in[6];
    const float* b2   = (const float*)d_in[7];
    float* out = (float*)d_out;

    int nnodes = in_sizes[0] / 3;
    int Qn = in_sizes[3] - 1;
    int ntiles = (Qn + QB - 1) / QB;
    int grid = 444;                     // 3 blocks/SM persistent
    if (grid > ntiles) grid = ntiles;

    prep_kernel<<<(nnodes + 255) / 256, 256>>>(geom, nnodes);
    moments_feat_kernel<<<((long long)Qn * 4 + 255) / 256, 256>>>(lq, nidx, rs, Qn);
    dummy_kernel<<<1, 32>>>();

    cudaFuncSetAttribute(mlp_kernel, cudaFuncAttributeMaxDynamicSharedMemorySize,
                         MLP_SMEM_BYTES);
    mlp_kernel<<<grid, NTH, MLP_SMEM_BYTES>>>(W1, b1, W2, b2, out, Qn, ntiles);
}

// round 12
// speedup vs baseline: 1.0733x; 1.0733x over previous
#include <cuda_runtime.h>
#include <cuda_bf16.h>
#include <math.h>

#define N_NODES_MAX 200000
#define N_QUERY_MAX 131072
#define FEAT 9
#define HID 64
#define OUT 128

typedef unsigned long long ull;

// ---------------- static device scratch ----------------
__device__ float4 g_geom4[N_NODES_MAX];
__device__ float  g_feat[FEAT * N_QUERY_MAX];   // column-major [FEAT][Q]
__device__ double g_sums[2 * FEAT];

// ---------------- f32x2 helpers ----------------
__device__ __forceinline__ ull pk2(float lo, float hi) {
    ull r; asm("mov.b64 %0,{%1,%2};" : "=l"(r) : "f"(lo), "f"(hi)); return r;
}
__device__ __forceinline__ void upk2(float& lo, float& hi, ull v) {
    asm("mov.b64 {%0,%1},%2;" : "=f"(lo), "=f"(hi) : "l"(v));
}
__device__ __forceinline__ ull fma2(ull a, ull b, ull c) {
    ull d; asm("fma.rn.f32x2 %0,%1,%2,%3;" : "=l"(d) : "l"(a), "l"(b), "l"(c));
    return d;
}

// ---------------- K1: pad geometry + zero accumulators ----------------
__global__ void prep_kernel(const float* __restrict__ geom, int n) {
    int i = blockIdx.x * blockDim.x + threadIdx.x;
    if (blockIdx.x == 0 && threadIdx.x < 2 * FEAT) g_sums[threadIdx.x] = 0.0;
    if (i < n) {
        float4 p;
        p.x = geom[3 * i + 0];
        p.y = geom[3 * i + 1];
        p.z = geom[3 * i + 2];
        p.w = 0.f;
        g_geom4[i] = p;
    }
}

// ---------------- dummy (profiler alignment) ----------------
__global__ void dummy_kernel() {}

// ---------------- K2: moments + features, 4 threads per query ----------------
__global__ __launch_bounds__(256)
void moments_feat_kernel(const float* __restrict__ lq,
                         const int* __restrict__ nidx,
                         const int* __restrict__ rs,
                         int Qn) {
    int t = blockIdx.x * blockDim.x + threadIdx.x;
    int q = t >> 2;
    int sub = t & 3;
    bool valid = (q < Qn);
    int qc = valid ? q : (Qn - 1);

    int start = rs[qc];
    int end   = rs[qc + 1];
    int cnt   = end - start;

    float qx = __ldg(&lq[3 * qc + 0]);
    float qy = __ldg(&lq[3 * qc + 1]);
    float qz = __ldg(&lq[3 * qc + 2]);

    float sd = 0.f, sd2 = 0.f;
    float sx = 0.f, sy = 0.f, sz = 0.f;
    float sxx = 0.f, sxy = 0.f, sxz = 0.f, syy = 0.f, syz = 0.f, szz = 0.f;

    if (cnt == 32 && (start & 3) == 0) {
        const int4* ip = (const int4*)(nidx + start) + sub * 2;
        int4 a = __ldg(ip), b = __ldg(ip + 1);
        int idf[8] = {a.x, a.y, a.z, a.w, b.x, b.y, b.z, b.w};
#pragma unroll
        for (int e = 0; e < 8; e++) {
            float4 p = g_geom4[idf[e]];
            float dx = p.x - qx, dy = p.y - qy, dz = p.z - qz;
            float d2 = dx * dx + dy * dy + dz * dz;
            sd  += sqrtf(d2);
            sd2 += d2;
            sx += p.x; sy += p.y; sz += p.z;
            sxx += p.x * p.x; sxy += p.x * p.y; sxz += p.x * p.z;
            syy += p.y * p.y; syz += p.y * p.z; szz += p.z * p.z;
        }
    } else {
        for (int e = start + sub; e < end; e += 4) {
            int id = __ldg(&nidx[e]);
            float4 p = g_geom4[id];
            float dx = p.x - qx, dy = p.y - qy, dz = p.z - qz;
            float d2 = dx * dx + dy * dy + dz * dz;
            sd  += sqrtf(d2);
            sd2 += d2;
            sx += p.x; sy += p.y; sz += p.z;
            sxx += p.x * p.x; sxy += p.x * p.y; sxz += p.x * p.z;
            syy += p.y * p.y; syz += p.y * p.z; szz += p.z * p.z;
        }
    }

#pragma unroll
    for (int o = 1; o <= 2; o <<= 1) {
        sd  += __shfl_xor_sync(0xffffffffu, sd, o);
        sd2 += __shfl_xor_sync(0xffffffffu, sd2, o);
        sx  += __shfl_xor_sync(0xffffffffu, sx, o);
        sy  += __shfl_xor_sync(0xffffffffu, sy, o);
        sz  += __shfl_xor_sync(0xffffffffu, sz, o);
        sxx += __shfl_xor_sync(0xffffffffu, sxx, o);
        sxy += __shfl_xor_sync(0xffffffffu, sxy, o);
        sxz += __shfl_xor_sync(0xffffffffu, sxz, o);
        syy += __shfl_xor_sync(0xffffffffu, syy, o);
        syz += __shfl_xor_sync(0xffffffffu, syz, o);
        szz += __shfl_xor_sync(0xffffffffu, szz, o);
    }

    float f[FEAT];
#pragma unroll
    for (int i = 0; i < FEAT; i++) f[i] = 0.f;

    __shared__ float sf[64][10];
    int row = threadIdx.x >> 2;

    if (sub == 0) {
        if (valid && cnt > 0) {
            float fcnt = (float)cnt;
            float inv = 1.f / fmaxf(fcnt, 1.f);

            float davg = sd * inv;
            float ex2  = sd2 * inv;
            float dvar = fmaxf(ex2 - davg * davg, 0.f);

            float cx = sx * inv, cy = sy * inv, cz = sz * inv;

            float a = sxx * inv - cx * cx;
            float b = syy * inv - cy * cy;
            float c = szz * inv - cz * cz;
            float d = sxy * inv - cx * cy;
            float e = sxz * inv - cx * cz;
            float ff = syz * inv - cy * cz;

            float e1, e2, e3;
            float p1 = d * d + e * e + ff * ff;
            float qm = (a + b + c) * (1.f / 3.f);
            float aa = a - qm, bb = b - qm, cc = c - qm;
            float p2 = aa * aa + bb * bb + cc * cc + 2.f * p1;
            if (p2 <= 1e-22f) {
                e1 = e2 = e3 = qm;
            } else {
                float p = sqrtf(p2 * (1.f / 6.f));
                float ipv = 1.f / p;
                float b11 = aa * ipv, b22 = bb * ipv, b33 = cc * ipv;
                float b12 = d * ipv, b13 = e * ipv, b23 = ff * ipv;
                float r = 0.5f * (b11 * (b22 * b33 - b23 * b23)
                                - b12 * (b12 * b33 - b23 * b13)
                                + b13 * (b12 * b23 - b22 * b13));
                r = fminf(fmaxf(r, -1.f), 1.f);
                float phi = acosf(r) * (1.f / 3.f);
                e1 = qm + 2.f * p * __cosf(phi);
                e3 = qm + 2.f * p * __cosf(phi + 2.0943951023931953f);
                e2 = 3.f * qm - e1 - e3;
            }

            f[0] = fcnt; f[1] = davg; f[2] = dvar;
            f[3] = cx - qx; f[4] = cy - qy; f[5] = cz - qz;
            f[6] = e1; f[7] = e2; f[8] = e3;
        }
        if (valid) {
#pragma unroll
            for (int i = 0; i < FEAT; i++) g_feat[i * N_QUERY_MAX + q] = f[i];
        }
#pragma unroll
        for (int i = 0; i < FEAT; i++) sf[row][i] = f[i];   // zeros if invalid
    }
    __syncthreads();

    int w = threadIdx.x >> 5, lane = threadIdx.x & 31;
    for (int c = w; c < FEAT; c += 8) {
        float a0 = sf[lane][c], a1 = sf[lane + 32][c];
        double s  = (double)a0 + (double)a1;
        double s2 = (double)a0 * a0 + (double)a1 * a1;
#pragma unroll
        for (int o = 16; o; o >>= 1) {
            s  += __shfl_xor_sync(0xffffffffu, s, o);
            s2 += __shfl_xor_sync(0xffffffffu, s2, o);
        }
        if (lane == 0) {
            atomicAdd(&g_sums[c], s);
            atomicAdd(&g_sums[FEAT + c], s2);
        }
    }
}

// ---------------- K3: MLP, R8 layout + forced 4 blocks/SM ----------------
// Layer2: warp = 8 queries, lane = 4 contiguous outputs.
//   per k: 1 lane-varying LDS.128 (W2, conflict-free) + 2 uniform LDS.128 (h)
//          + 8 pk2 (alu pipe, non-binding) + 16 fma2
#define QB 64
#define NTH 256
#define OFF_W2   0                      // 64*128 = 8192
#define OFF_W1   (OFF_W2 + HID * OUT)   // 576
#define OFF_B1   (OFF_W1 + FEAT * HID)  // 64
#define OFF_B2   (OFF_B1 + HID)         // 128
#define OFF_NRM  (OFF_B2 + OUT)         // 32
#define OFF_H    (OFF_NRM + 32)         // 64*64 = 4096
#define MLP_SMEM_FLOATS (OFF_H + HID * QB)
#define MLP_SMEM_BYTES  (MLP_SMEM_FLOATS * 4)

__global__ __launch_bounds__(NTH, 4)
void mlp_kernel(const float* __restrict__ gW1, const float* __restrict__ gb1,
                const float* __restrict__ gW2, const float* __restrict__ gb2,
                float* __restrict__ out, int Qn) {
    extern __shared__ float sm[];
    int tid = threadIdx.x;

    {
        const float4* w2v = (const float4*)gW2;
        float4* d = (float4*)&sm[OFF_W2];
#pragma unroll
        for (int i = 0; i < (HID * OUT / 4) / NTH; i++)
            d[tid + i * NTH] = w2v[tid + i * NTH];
        for (int i = tid; i < FEAT * HID; i += NTH) sm[OFF_W1 + i] = gW1[i];
        if (tid < HID) sm[OFF_B1 + tid] = gb1[tid];
        if (tid < OUT) sm[OFF_B2 + tid] = gb2[tid];
        if (tid < FEAT) {
            double Qd = (double)Qn;
            double mean = g_sums[tid] / Qd;
            double var = (g_sums[FEAT + tid] - Qd * mean * mean) / (Qd - 1.0);
            if (var < 0.0) var = 0.0;
            double sd = sqrt(var);
            sm[OFF_NRM + tid] = (float)mean;
            sm[OFF_NRM + FEAT + tid] = (sd < 1e-6) ? 1.0f : (float)(1.0 / sd);
        }
    }
    __syncthreads();

    int qb = blockIdx.x * QB;

    // ---------- layer 1: 4 threads per query, 16 h-outputs each ----------
    {
        int ql = tid & (QB - 1);
        int quarter = tid >> 6;        // 0..3
        int q = qb + ql;
        int qc = (q < Qn) ? q : (Qn - 1);

        ull fnp[FEAT];
#pragma unroll
        for (int i = 0; i < FEAT; i++) {
            float v = (g_feat[i * N_QUERY_MAX + qc] - sm[OFF_NRM + i]) * sm[OFF_NRM + FEAT + i];
            fnp[i] = pk2(v, v);
        }

        float* hs = &sm[OFF_H];
        int ob = quarter * 16;
#pragma unroll
        for (int op = 0; op < 8; op++) {
            int o = ob + 2 * op;
            ull acc = *(const ull*)&sm[OFF_B1 + o];
#pragma unroll
            for (int ffi = 0; ffi < FEAT; ffi++)
                acc = fma2(fnp[ffi], *(const ull*)&sm[OFF_W1 + ffi * HID + o], acc);
            float lo, hi; upk2(lo, hi, acc);
            hs[o * QB + ql]       = fmaxf(lo, 0.f);
            hs[(o + 1) * QB + ql] = fmaxf(hi, 0.f);
        }
    }
    __syncthreads();

    // ---------- layer 2: warp = 8 queries, lane = 4 outputs ----------
    int w = tid >> 5;        // warp 0..7 -> queries [w*8, w*8+8)
    int lane = tid & 31;     // outputs [lane*4, lane*4+4)

    const float* hsb = &sm[OFF_H + w * 8];
    const float* w2b = &sm[OFF_W2 + lane * 4];

    ull acc[8][2];
    {
        ulonglong2 bz = *(const ulonglong2*)&sm[OFF_B2 + lane * 4];
#pragma unroll
        for (int q8 = 0; q8 < 8; q8++) { acc[q8][0] = bz.x; acc[q8][1] = bz.y; }
    }

#pragma unroll 8
    for (int k = 0; k < HID; k++) {
        // lane-varying W2 chunk: contiguous 512B per warp, conflict-free
        ulonglong2 wv = *(const ulonglong2*)&w2b[k * OUT];
        // uniform h for this warp's 8 queries (2 broadcast LDS.128)
        float4 h0 = *(const float4*)&hsb[k * QB];
        float4 h1 = *(const float4*)&hsb[k * QB + 4];
        float hq[8] = {h0.x, h0.y, h0.z, h0.w, h1.x, h1.y, h1.z, h1.w};
#pragma unroll
        for (int q8 = 0; q8 < 8; q8++) {
            ull hk = pk2(hq[q8], hq[q8]);
            acc[q8][0] = fma2(hk, wv.x, acc[q8][0]);
            acc[q8][1] = fma2(hk, wv.y, acc[q8][1]);
        }
    }

    // epilogue: relu + perfectly coalesced stores (512B contiguous per query)
#pragma unroll
    for (int q8 = 0; q8 < 8; q8++) {
        int gq = qb + w * 8 + q8;
        if (gq < Qn) {
            float a0, a1, a2, a3;
            upk2(a0, a1, acc[q8][0]);
            upk2(a2, a3, acc[q8][1]);
            float4 r;
            r.x = fmaxf(a0, 0.f); r.y = fmaxf(a1, 0.f);
            r.z = fmaxf(a2, 0.f); r.w = fmaxf(a3, 0.f);
            *(float4*)&out[(size_t)gq * OUT + lane * 4] = r;
        }
    }
}

// ---------------- launch ----------------
// Launch order: prep(0), moments(1), dummy(2), mlp(3) -> ncu profiles mlp.
extern "C" void kernel_launch(void* const* d_in, const int* in_sizes, int n_in,
                              void* d_out, int out_size) {
    const float* geom = (const float*)d_in[0];
    const float* lq   = (const float*)d_in[1];
    const int*   nidx = (const int*)d_in[2];
    const int*   rs   = (const int*)d_in[3];
    const float* W1   = (const float*)d_in[4];
    const float* b1   = (const float*)d_in[5];
    const float* W2   = (const float*)d_in[6];
    const float* b2   = (const float*)d_in[7];
    float* out = (float*)d_out;

    int nnodes = in_sizes[0] / 3;
    int Qn = in_sizes[3] - 1;

    prep_kernel<<<(nnodes + 255) / 256, 256>>>(geom, nnodes);
    moments_feat_kernel<<<((long long)Qn * 4 + 255) / 256, 256>>>(lq, nidx, rs, Qn);
    dummy_kernel<<<1, 32>>>();

    cudaFuncSetAttribute(mlp_kernel, cudaFuncAttributeMaxDynamicSharedMemorySize,
                         MLP_SMEM_BYTES);
    mlp_kernel<<<(Qn + QB - 1) / QB, NTH, MLP_SMEM_BYTES>>>(W1, b1, W2, b2, out, Qn);
}